// round 1
// baseline (speedup 1.0000x reference)
#include <cuda_runtime.h>
#include <math.h>
#include <stdint.h>

// Problem constants
#define Dm   2048
#define Nh   16
#define Kh   8
#define Hd   128
#define Ff   8192
#define Bb   2
#define T0c  1024
#define T1c  1024
#define TOTc 2048

// ---------------- scratch (static device globals; no allocation) ----------
__device__ float g_pre [(size_t)Bb*TOTc*Dm];        // rmsnorm(x) [B,TOT,D]
__device__ float g_q   [(size_t)Bb*TOTc*Nh*Hd];     // Q [B,TOT,N*H]
__device__ float g_k   [(size_t)Bb*TOTc*Kh*Hd];     // K [B,TOT,K*H]
__device__ float g_v   [(size_t)Bb*TOTc*Kh*Hd];     // V [B,TOT,K*H]
__device__ float g_enc [(size_t)Bb*TOTc*Nh*Hd];     // attention out [B,TOT,N*H]
__device__ float g_res [(size_t)Bb*TOTc*Dm];        // residual [B,TOT,D]
__device__ float g_hid [(size_t)Bb*TOTc*Dm];        // rmsnorm(residual)
__device__ float g_gu  [(size_t)Bb*T0c*Ff];         // gelu(gate)*up, per-segment reuse

// row remap: local row r (segment-contiguous, T rows per batch) -> physical row
// in a [B, TT, ...] layout at time offset `off`.
__device__ __forceinline__ int maprow(int r, int T, int TT, int off) {
    return (r / T) * TT + (r % T) + off;
}

// ---------------- RMSNorm ----------------
__global__ void rmsnorm_k(const float* __restrict__ x, const float* __restrict__ sc,
                          float* __restrict__ out,
                          int iT, int iTT, int iOff, int oT, int oTT, int oOff)
{
    int r = blockIdx.x;
    const float* xi = x + (size_t)maprow(r, iT, iTT, iOff) * Dm;
    float* o = out + (size_t)maprow(r, oT, oTT, oOff) * Dm;
    __shared__ float red[256];
    float s = 0.f;
    for (int d = threadIdx.x; d < Dm; d += 256) { float v = xi[d]; s += v * v; }
    red[threadIdx.x] = s;
    __syncthreads();
    for (int st = 128; st > 0; st >>= 1) {
        if (threadIdx.x < st) red[threadIdx.x] += red[threadIdx.x + st];
        __syncthreads();
    }
    float inv = rsqrtf(red[0] / (float)Dm + 1e-6f);
    for (int d = threadIdx.x; d < Dm; d += 256)
        o[d] = xi[d] * inv * (1.f + sc[d]);
}

// ---------------- RoPE (in-place), optional output scale ----------------
__global__ void rope_k(float* __restrict__ x, const int* __restrict__ pos,
                       int nheads, float scale)
{
    int blk  = blockIdx.x;
    int head = blk % nheads;
    int bt   = blk / nheads;           // b*TOT + t
    float p  = (float)pos[bt];
    float* v = x + ((size_t)bt * nheads + head) * Hd;
    int h = threadIdx.x;               // 0..63
    float fe = (2.f / (float)Hd) * (float)h;
    // 10000^fe  -> exp2(fe * log2(10000))
    float inv_ts = exp2f(-fe * 13.287712379549449f);
    float rad = p * inv_ts;
    float s, c;
    sincosf(rad, &s, &c);
    float x1 = v[h], x2 = v[h + 64];
    v[h]      = (x1 * c - x2 * s) * scale;
    v[h + 64] = (x2 * c + x1 * s) * scale;
}

// ---------------- generic tiled GEMM: C = A * W^T (+ R) ----------------
// A: M x Kin (rows via maprow a*), W: Nout x Kin row-major,
// C rows via maprow c*, optional R rows via maprow r*.
__global__ void gemm64(const float* __restrict__ A, const float* __restrict__ W,
                       float* __restrict__ C, const float* __restrict__ R,
                       int M, int Nout, int Kin,
                       int aT, int aTT, int aOff,
                       int cT, int cTT, int cOff,
                       int rT, int rTT, int rOff, int addR)
{
    __shared__ float As[16][64];
    __shared__ float Ws[16][64];
    int tid = threadIdx.x;
    int bm = blockIdx.y * 64, bn = blockIdx.x * 64;
    int lr = tid >> 2;              // 0..63
    int lk = (tid & 3) << 2;        // 0,4,8,12
    const float* aptr = A + (size_t)maprow(bm + lr, aT, aTT, aOff) * Kin + lk;
    const float* wptr = W + (size_t)(bn + lr) * Kin + lk;
    int ty = tid >> 4, tx = tid & 15;
    float acc[4][4];
#pragma unroll
    for (int i = 0; i < 4; i++)
#pragma unroll
        for (int j = 0; j < 4; j++) acc[i][j] = 0.f;

    for (int k0 = 0; k0 < Kin; k0 += 16) {
        float4 av = *(const float4*)(aptr + k0);
        float4 wv = *(const float4*)(wptr + k0);
        As[lk + 0][lr] = av.x; As[lk + 1][lr] = av.y;
        As[lk + 2][lr] = av.z; As[lk + 3][lr] = av.w;
        Ws[lk + 0][lr] = wv.x; Ws[lk + 1][lr] = wv.y;
        Ws[lk + 2][lr] = wv.z; Ws[lk + 3][lr] = wv.w;
        __syncthreads();
#pragma unroll
        for (int kk = 0; kk < 16; kk++) {
            float4 a4 = *(const float4*)&As[kk][ty * 4];
            float4 b4 = *(const float4*)&Ws[kk][tx * 4];
            float a[4] = {a4.x, a4.y, a4.z, a4.w};
            float b[4] = {b4.x, b4.y, b4.z, b4.w};
#pragma unroll
            for (int i = 0; i < 4; i++)
#pragma unroll
                for (int j = 0; j < 4; j++) acc[i][j] += a[i] * b[j];
        }
        __syncthreads();
    }
#pragma unroll
    for (int i = 0; i < 4; i++) {
        int r = bm + ty * 4 + i;
        float* cp = C + (size_t)maprow(r, cT, cTT, cOff) * Nout + bn + tx * 4;
        float4 o;
        o.x = acc[i][0]; o.y = acc[i][1]; o.z = acc[i][2]; o.w = acc[i][3];
        if (addR) {
            const float* rp = R + (size_t)maprow(r, rT, rTT, rOff) * Nout + bn + tx * 4;
            o.x += rp[0]; o.y += rp[1]; o.z += rp[2]; o.w += rp[3];
        }
        *(float4*)cp = o;
    }
}

// ---------------- dual GEMM: C = gelu(A*W1^T) * (A*W2^T) ----------------
__device__ __forceinline__ float gelu_t(float x) {
    float x3 = x * x * x;
    float t = tanhf(0.7978845608028654f * (x + 0.044715f * x3));
    return 0.5f * x * (1.f + t);
}

__global__ void dualgemm64(const float* __restrict__ A, const float* __restrict__ W1,
                           const float* __restrict__ W2, float* __restrict__ C,
                           int M, int Nout, int Kin,
                           int aT, int aTT, int aOff,
                           int cT, int cTT, int cOff)
{
    __shared__ float As[16][64];
    __shared__ float W1s[16][64];
    __shared__ float W2s[16][64];
    int tid = threadIdx.x;
    int bm = blockIdx.y * 64, bn = blockIdx.x * 64;
    int lr = tid >> 2;
    int lk = (tid & 3) << 2;
    const float* aptr  = A  + (size_t)maprow(bm + lr, aT, aTT, aOff) * Kin + lk;
    const float* w1ptr = W1 + (size_t)(bn + lr) * Kin + lk;
    const float* w2ptr = W2 + (size_t)(bn + lr) * Kin + lk;
    int ty = tid >> 4, tx = tid & 15;
    float acc1[4][4], acc2[4][4];
#pragma unroll
    for (int i = 0; i < 4; i++)
#pragma unroll
        for (int j = 0; j < 4; j++) { acc1[i][j] = 0.f; acc2[i][j] = 0.f; }

    for (int k0 = 0; k0 < Kin; k0 += 16) {
        float4 av = *(const float4*)(aptr + k0);
        float4 w1 = *(const float4*)(w1ptr + k0);
        float4 w2 = *(const float4*)(w2ptr + k0);
        As [lk + 0][lr] = av.x; As [lk + 1][lr] = av.y; As [lk + 2][lr] = av.z; As [lk + 3][lr] = av.w;
        W1s[lk + 0][lr] = w1.x; W1s[lk + 1][lr] = w1.y; W1s[lk + 2][lr] = w1.z; W1s[lk + 3][lr] = w1.w;
        W2s[lk + 0][lr] = w2.x; W2s[lk + 1][lr] = w2.y; W2s[lk + 2][lr] = w2.z; W2s[lk + 3][lr] = w2.w;
        __syncthreads();
#pragma unroll
        for (int kk = 0; kk < 16; kk++) {
            float4 a4 = *(const float4*)&As[kk][ty * 4];
            float4 b4 = *(const float4*)&W1s[kk][tx * 4];
            float4 c4 = *(const float4*)&W2s[kk][tx * 4];
            float a[4] = {a4.x, a4.y, a4.z, a4.w};
            float b[4] = {b4.x, b4.y, b4.z, b4.w};
            float c[4] = {c4.x, c4.y, c4.z, c4.w};
#pragma unroll
            for (int i = 0; i < 4; i++)
#pragma unroll
                for (int j = 0; j < 4; j++) {
                    acc1[i][j] += a[i] * b[j];
                    acc2[i][j] += a[i] * c[j];
                }
        }
        __syncthreads();
    }
#pragma unroll
    for (int i = 0; i < 4; i++) {
        int r = bm + ty * 4 + i;
        float* cp = C + (size_t)maprow(r, cT, cTT, cOff) * Nout + bn + tx * 4;
        float4 o;
        o.x = gelu_t(acc1[i][0]) * acc2[i][0];
        o.y = gelu_t(acc1[i][1]) * acc2[i][1];
        o.z = gelu_t(acc1[i][2]) * acc2[i][2];
        o.w = gelu_t(acc1[i][3]) * acc2[i][3];
        *(float4*)cp = o;
    }
}

// ---------------- attention: causal GQA, online softmax ----------------
// block = (b, head n, 16-query tile); 256 threads.
#define TQ 16
#define TS 32
__global__ void attn_k(const float* __restrict__ Q, const float* __restrict__ Kb,
                       const float* __restrict__ Vb, float* __restrict__ enc)
{
    __shared__ float Qs[TQ][Hd];
    __shared__ float Ks[TS][Hd + 4];
    __shared__ float Vs[TS][Hd + 4];
    __shared__ float Ps[TQ][TS];
    int b = blockIdx.z, n = blockIdx.y, tq0 = blockIdx.x * TQ;
    int kh = n >> 1;   // G = 2
    int tid = threadIdx.x;

    // load Q tile (16 x 128)
    for (int i = tid; i < TQ * Hd / 4; i += 256) {
        int q = (i * 4) / Hd, col = (i * 4) % Hd;
        *(float4*)&Qs[q][col] =
            *(const float4*)&Q[(((size_t)b * TOTc) + tq0 + q) * (Nh * Hd) + (size_t)n * Hd + col];
    }
    int q = tid >> 4, lane = tid & 15;
    float m = -3.0e38f, l = 0.f;
    float acc[8];
#pragma unroll
    for (int j = 0; j < 8; j++) acc[j] = 0.f;
    int tmax = tq0 + TQ - 1;
    int t = tq0 + q;
    __syncthreads();

    for (int s0 = 0; s0 <= tmax; s0 += TS) {
        // load K/V tile (32 x 128 each)
        for (int i = tid; i < TS * Hd / 4; i += 256) {
            int srow = (i * 4) / Hd, col = (i * 4) % Hd;
            size_t gidx = (((size_t)b * TOTc) + s0 + srow) * (Kh * Hd) + (size_t)kh * Hd + col;
            *(float4*)&Ks[srow][col] = *(const float4*)&Kb[gidx];
            *(float4*)&Vs[srow][col] = *(const float4*)&Vb[gidx];
        }
        __syncthreads();

        // scores: this thread covers s = lane and lane+16
        float sc0 = 0.f, sc1 = 0.f;
#pragma unroll 4
        for (int kk = 0; kk < Hd; kk++) {
            float qv = Qs[q][kk];
            sc0 += qv * Ks[lane][kk];
            sc1 += qv * Ks[lane + 16][kk];
        }
        if (s0 + lane > t)      sc0 = -3.0e38f;
        if (s0 + lane + 16 > t) sc1 = -3.0e38f;

        // group max over 16 lanes (contiguous within warp)
        float mx = fmaxf(sc0, sc1);
#pragma unroll
        for (int o = 8; o > 0; o >>= 1)
            mx = fmaxf(mx, __shfl_xor_sync(0xffffffffu, mx, o));
        float nm = fmaxf(m, mx);
        float p0 = expf(sc0 - nm), p1 = expf(sc1 - nm);
        float scale = expf(m - nm);
        float ssum = p0 + p1;
#pragma unroll
        for (int o = 8; o > 0; o >>= 1)
            ssum += __shfl_xor_sync(0xffffffffu, ssum, o);
        l = l * scale + ssum;
        m = nm;
        Ps[q][lane] = p0;
        Ps[q][lane + 16] = p1;
        __syncwarp();

#pragma unroll
        for (int j = 0; j < 8; j++) acc[j] *= scale;
        for (int s = 0; s < TS; s++) {
            float pv = Ps[q][s];
#pragma unroll
            for (int j = 0; j < 8; j++) acc[j] += pv * Vs[s][lane * 8 + j];
        }
        __syncthreads();
    }

    float invl = 1.f / l;
    float* op = enc + (((size_t)b * TOTc) + t) * (Nh * Hd) + (size_t)n * Hd + lane * 8;
#pragma unroll
    for (int j = 0; j < 8; j++) op[j] = acc[j] * invl;
}

// ---------------- host orchestration ----------------
extern "C" void kernel_launch(void* const* d_in, const int* in_sizes, int n_in,
                              void* d_out, int out_size)
{
    (void)in_sizes; (void)n_in; (void)out_size;
    const float* xs[2] = {(const float*)d_in[0], (const float*)d_in[1]};
    const int*   pos   = (const int*)d_in[2];
    // d_in[3] = mask: always causal lower-triangular (computed in-kernel)
    const float* qw[2] = {(const float*)d_in[4],  (const float*)d_in[5]};
    const float* kw[2] = {(const float*)d_in[6],  (const float*)d_in[7]};
    const float* vw[2] = {(const float*)d_in[8],  (const float*)d_in[9]};
    const float* ow[2] = {(const float*)d_in[10], (const float*)d_in[11]};
    const float* gw[2] = {(const float*)d_in[12], (const float*)d_in[13]};
    const float* uw[2] = {(const float*)d_in[14], (const float*)d_in[15]};
    const float* dwn[2]= {(const float*)d_in[16], (const float*)d_in[17]};
    const float* pa[2] = {(const float*)d_in[18], (const float*)d_in[19]};
    const float* pf[2] = {(const float*)d_in[20], (const float*)d_in[21]};
    float* out = (float*)d_out;

    float *pre, *qb, *kb, *vb, *enc, *res, *hid, *gu;
    cudaGetSymbolAddress((void**)&pre, g_pre);
    cudaGetSymbolAddress((void**)&qb,  g_q);
    cudaGetSymbolAddress((void**)&kb,  g_k);
    cudaGetSymbolAddress((void**)&vb,  g_v);
    cudaGetSymbolAddress((void**)&enc, g_enc);
    cudaGetSymbolAddress((void**)&res, g_res);
    cudaGetSymbolAddress((void**)&hid, g_hid);
    cudaGetSymbolAddress((void**)&gu,  g_gu);

    const int Ts[2]   = {T0c, T1c};
    const int offs[2] = {0, T0c};

    // 1) pre-attention RMSNorm
    for (int s = 0; s < 2; s++)
        rmsnorm_k<<<Bb * Ts[s], 256>>>(xs[s], pa[s], pre,
                                       Ts[s], Ts[s], 0, Ts[s], TOTc, offs[s]);

    // 2) QKV projections per segment
    for (int s = 0; s < 2; s++) {
        int off = offs[s], M = Bb * Ts[s];
        gemm64<<<dim3((Nh * Hd) / 64, M / 64), 256>>>(
            pre, qw[s], qb, nullptr, M, Nh * Hd, Dm,
            Ts[s], TOTc, off, Ts[s], TOTc, off, 1, 1, 0, 0);
        gemm64<<<dim3((Kh * Hd) / 64, M / 64), 256>>>(
            pre, kw[s], kb, nullptr, M, Kh * Hd, Dm,
            Ts[s], TOTc, off, Ts[s], TOTc, off, 1, 1, 0, 0);
        gemm64<<<dim3((Kh * Hd) / 64, M / 64), 256>>>(
            pre, vw[s], vb, nullptr, M, Kh * Hd, Dm,
            Ts[s], TOTc, off, Ts[s], TOTc, off, 1, 1, 0, 0);
    }

    // 3) RoPE (Q gets 1/sqrt(H) folded in)
    rope_k<<<Bb * TOTc * Nh, 64>>>(qb, pos, Nh, 0.08838834764831845f);
    rope_k<<<Bb * TOTc * Kh, 64>>>(kb, pos, Kh, 1.0f);

    // 4) attention
    attn_k<<<dim3(TOTc / TQ, Nh, Bb), 256>>>(qb, kb, vb, enc);

    // 5) O projection + residual add of x
    for (int s = 0; s < 2; s++) {
        int off = offs[s], M = Bb * Ts[s];
        gemm64<<<dim3(Dm / 64, M / 64), 256>>>(
            enc, ow[s], res, xs[s], M, Dm, Nh * Hd,
            Ts[s], TOTc, off, Ts[s], TOTc, off, Ts[s], Ts[s], 0, 1);
    }

    // 6) pre-FFN RMSNorm
    for (int s = 0; s < 2; s++)
        rmsnorm_k<<<Bb * Ts[s], 256>>>(res, pf[s], hid,
                                       Ts[s], TOTc, offs[s], Ts[s], TOTc, offs[s]);

    // 7) FFN per segment: dual gemm (gelu(gate)*up), then down proj + residual -> out
    for (int s = 0; s < 2; s++) {
        int off = offs[s], M = Bb * Ts[s];
        dualgemm64<<<dim3(Ff / 64, M / 64), 256>>>(
            hid, gw[s], uw[s], gu, M, Ff, Dm,
            Ts[s], TOTc, off, Ts[s], Ts[s], 0);
        float* outseg = out + (size_t)offs[s] * Bb * Dm;  // seg1 starts at B*T0*D
        gemm64<<<dim3(Dm / 64, M / 64), 256>>>(
            gu, dwn[s], outseg, res, M, Dm, Ff,
            Ts[s], Ts[s], 0, Ts[s], Ts[s], 0, Ts[s], TOTc, off, 1);
    }
}

// round 2
// speedup vs baseline: 3.0413x; 3.0413x over previous
#include <cuda_runtime.h>
#include <math.h>
#include <stdint.h>

// Problem constants
#define Dm   2048
#define Nh   16
#define Kh   8
#define Hd   128
#define Ff   8192
#define Bb   2
#define T0c  1024
#define T1c  1024
#define TOTc 2048

// ---------------- scratch (static device globals; no allocation) ----------
__device__ float g_pre [(size_t)Bb*TOTc*Dm];
__device__ float g_q   [(size_t)Bb*TOTc*Nh*Hd];
__device__ float g_k   [(size_t)Bb*TOTc*Kh*Hd];
__device__ float g_v   [(size_t)Bb*TOTc*Kh*Hd];
__device__ float g_enc [(size_t)Bb*TOTc*Nh*Hd];
__device__ float g_res [(size_t)Bb*TOTc*Dm];
__device__ float g_hid [(size_t)Bb*TOTc*Dm];
__device__ float g_gate[(size_t)Bb*T0c*Ff];
__device__ float g_up  [(size_t)Bb*T0c*Ff];

__device__ __forceinline__ int maprow(int r, int T, int TT, int off) {
    return (r / T) * TT + (r % T) + off;
}

__device__ __forceinline__ unsigned f2tf32(float x) {
    unsigned r;
    asm("cvt.rna.tf32.f32 %0, %1;" : "=r"(r) : "f"(x));
    return r;
}

__device__ __forceinline__ void mma8(float* c, const unsigned* a, unsigned b0, unsigned b1) {
    asm volatile(
        "mma.sync.aligned.m16n8k8.row.col.f32.tf32.tf32.f32 "
        "{%0,%1,%2,%3},{%4,%5,%6,%7},{%8,%9},{%0,%1,%2,%3};"
        : "+f"(c[0]), "+f"(c[1]), "+f"(c[2]), "+f"(c[3])
        : "r"(a[0]), "r"(a[1]), "r"(a[2]), "r"(a[3]), "r"(b0), "r"(b1));
}

// ---------------- RMSNorm ----------------
__global__ void rmsnorm_k(const float* __restrict__ x, const float* __restrict__ sc,
                          float* __restrict__ out,
                          int iT, int iTT, int iOff, int oT, int oTT, int oOff)
{
    int r = blockIdx.x;
    const float* xi = x + (size_t)maprow(r, iT, iTT, iOff) * Dm;
    float* o = out + (size_t)maprow(r, oT, oTT, oOff) * Dm;
    __shared__ float red[256];
    float s = 0.f;
    for (int d = threadIdx.x; d < Dm; d += 256) { float v = xi[d]; s += v * v; }
    red[threadIdx.x] = s;
    __syncthreads();
    for (int st = 128; st > 0; st >>= 1) {
        if (threadIdx.x < st) red[threadIdx.x] += red[threadIdx.x + st];
        __syncthreads();
    }
    float inv = rsqrtf(red[0] / (float)Dm + 1e-6f);
    for (int d = threadIdx.x; d < Dm; d += 256)
        o[d] = xi[d] * inv * (1.f + sc[d]);
}

// ---------------- RoPE (in-place), optional output scale ----------------
__global__ void rope_k(float* __restrict__ x, const int* __restrict__ pos,
                       int nheads, float scale)
{
    int blk  = blockIdx.x;
    int head = blk % nheads;
    int bt   = blk / nheads;
    float p  = (float)pos[bt];
    float* v = x + ((size_t)bt * nheads + head) * Hd;
    int h = threadIdx.x;               // 0..63
    float fe = (2.f / (float)Hd) * (float)h;
    float inv_ts = exp2f(-fe * 13.287712379549449f);
    float rad = p * inv_ts;
    float s, c;
    sincosf(rad, &s, &c);
    float x1 = v[h], x2 = v[h + 64];
    v[h]      = (x1 * c - x2 * s) * scale;
    v[h + 64] = (x2 * c + x1 * s) * scale;
}

// ---------------- tf32 tensor-core GEMM: C = A * W^T (+ R) ----------------
// CTA tile 128x128, BK=16, double-buffered. 256 threads = 8 warps (2m x 4n),
// warp tile 64x32 = 4 m-tiles x 4 n-tiles of m16n8k8.
#define GPAD 20
__global__ __launch_bounds__(256, 2)
void gemm_tc(const float* __restrict__ A, const float* __restrict__ W,
             float* __restrict__ C, const float* __restrict__ R,
             int Nout, int Kin,
             int aT, int aTT, int aOff,
             int cT, int cTT, int cOff,
             int rT, int rTT, int rOff, int addR)
{
    __shared__ unsigned As[2][128 * GPAD];
    __shared__ unsigned Bs[2][128 * GPAD];
    const int tid  = threadIdx.x;
    const int bm   = blockIdx.y * 128, bn = blockIdx.x * 128;
    const int warp = tid >> 5, lane = tid & 31;
    const int wm   = (warp & 1) * 64;
    const int wn   = (warp >> 1) * 32;
    const int r0   = lane >> 2, c0 = lane & 3;

    // global load mapping: each thread loads 8 A floats + 8 B floats per k-step
    const int grow = tid >> 1;          // 0..127
    const int gcol = (tid & 1) * 8;     // 0 or 8
    const float* aP = A + (size_t)maprow(bm + grow, aT, aTT, aOff) * Kin + gcol;
    const float* bP = W + (size_t)(bn + grow) * Kin + gcol;
    const int sW = grow * GPAD + gcol;  // smem write offset within a buffer

    float acc[4][4][4];
#pragma unroll
    for (int mt = 0; mt < 4; mt++)
#pragma unroll
        for (int nt = 0; nt < 4; nt++)
#pragma unroll
            for (int i = 0; i < 4; i++) acc[mt][nt][i] = 0.f;

    const int nk = Kin / 16;

    // prologue: tile 0 -> buffer 0
    {
        float4 a0 = *(const float4*)(aP);
        float4 a1 = *(const float4*)(aP + 4);
        float4 b0 = *(const float4*)(bP);
        float4 b1 = *(const float4*)(bP + 4);
        unsigned* aw = &As[0][sW];
        unsigned* bw = &Bs[0][sW];
        aw[0]=f2tf32(a0.x); aw[1]=f2tf32(a0.y); aw[2]=f2tf32(a0.z); aw[3]=f2tf32(a0.w);
        aw[4]=f2tf32(a1.x); aw[5]=f2tf32(a1.y); aw[6]=f2tf32(a1.z); aw[7]=f2tf32(a1.w);
        bw[0]=f2tf32(b0.x); bw[1]=f2tf32(b0.y); bw[2]=f2tf32(b0.z); bw[3]=f2tf32(b0.w);
        bw[4]=f2tf32(b1.x); bw[5]=f2tf32(b1.y); bw[6]=f2tf32(b1.z); bw[7]=f2tf32(b1.w);
    }
    __syncthreads();

    for (int kt = 0; kt < nk; kt++) {
        const unsigned* as = As[kt & 1];
        const unsigned* bs = Bs[kt & 1];
        float4 na0, na1, nb0, nb1;
        const bool more = (kt + 1 < nk);
        if (more) {
            const float* ap = aP + (size_t)(kt + 1) * 16;
            const float* bp = bP + (size_t)(kt + 1) * 16;
            na0 = *(const float4*)(ap);
            na1 = *(const float4*)(ap + 4);
            nb0 = *(const float4*)(bp);
            nb1 = *(const float4*)(bp + 4);
        }
#pragma unroll
        for (int ks = 0; ks < 2; ks++) {
            unsigned af[4][4], bf[4][2];
#pragma unroll
            for (int mt = 0; mt < 4; mt++) {
                int base = (wm + mt * 16 + r0) * GPAD + ks * 8 + c0;
                af[mt][0] = as[base];
                af[mt][1] = as[base + 8 * GPAD];
                af[mt][2] = as[base + 4];
                af[mt][3] = as[base + 8 * GPAD + 4];
            }
#pragma unroll
            for (int nt = 0; nt < 4; nt++) {
                int base = (wn + nt * 8 + r0) * GPAD + ks * 8 + c0;
                bf[nt][0] = bs[base];
                bf[nt][1] = bs[base + 4];
            }
#pragma unroll
            for (int mt = 0; mt < 4; mt++)
#pragma unroll
                for (int nt = 0; nt < 4; nt++)
                    mma8(acc[mt][nt], af[mt], bf[nt][0], bf[nt][1]);
        }
        if (more) {
            unsigned* aw = &As[(kt + 1) & 1][sW];
            unsigned* bw = &Bs[(kt + 1) & 1][sW];
            aw[0]=f2tf32(na0.x); aw[1]=f2tf32(na0.y); aw[2]=f2tf32(na0.z); aw[3]=f2tf32(na0.w);
            aw[4]=f2tf32(na1.x); aw[5]=f2tf32(na1.y); aw[6]=f2tf32(na1.z); aw[7]=f2tf32(na1.w);
            bw[0]=f2tf32(nb0.x); bw[1]=f2tf32(nb0.y); bw[2]=f2tf32(nb0.z); bw[3]=f2tf32(nb0.w);
            bw[4]=f2tf32(nb1.x); bw[5]=f2tf32(nb1.y); bw[6]=f2tf32(nb1.z); bw[7]=f2tf32(nb1.w);
        }
        __syncthreads();
    }

    // epilogue
#pragma unroll
    for (int mt = 0; mt < 4; mt++) {
        int r  = bm + wm + mt * 16 + r0;
        int pr = maprow(r, cT, cTT, cOff);
        int rr = addR ? maprow(r, rT, rTT, rOff) : 0;
#pragma unroll
        for (int nt = 0; nt < 4; nt++) {
            int cc = bn + wn + nt * 8 + 2 * c0;
            float2 v0 = make_float2(acc[mt][nt][0], acc[mt][nt][1]);
            float2 v1 = make_float2(acc[mt][nt][2], acc[mt][nt][3]);
            if (addR) {
                float2 u0 = *(const float2*)&R[(size_t)rr * Nout + cc];
                float2 u1 = *(const float2*)&R[(size_t)(rr + 8) * Nout + cc];
                v0.x += u0.x; v0.y += u0.y;
                v1.x += u1.x; v1.y += u1.y;
            }
            *(float2*)&C[(size_t)pr * Nout + cc]       = v0;
            *(float2*)&C[(size_t)(pr + 8) * Nout + cc] = v1;
        }
    }
}

// ---------------- gelu(gate) * up ----------------
__device__ __forceinline__ float gelu_t(float x) {
    float x3 = x * x * x;
    float t = tanhf(0.7978845608028654f * (x + 0.044715f * x3));
    return 0.5f * x * (1.f + t);
}

__global__ void gelumul_k(const float* __restrict__ g, const float* __restrict__ u,
                          float* __restrict__ o, int n4)
{
    int i = blockIdx.x * 256 + threadIdx.x;
    if (i >= n4) return;
    float4 gg = ((const float4*)g)[i];
    float4 uu = ((const float4*)u)[i];
    float4 oo;
    oo.x = gelu_t(gg.x) * uu.x;
    oo.y = gelu_t(gg.y) * uu.y;
    oo.z = gelu_t(gg.z) * uu.z;
    oo.w = gelu_t(gg.w) * uu.w;
    ((float4*)o)[i] = oo;
}

// ---------------- attention: flash-style, tf32 mma ----------------
// block = (b, head, 64-query tile); 128 threads = 4 warps, 16 q-rows per warp.
// KV tiles of 32. Q kept in register fragments. K/V stored in smem as tf32 bits
// with row stride 136 (conflict-free B-fragment banks). P goes through per-warp
// smem (stride 36, conflict-free A-fragment banks).
#define ATQ 64
#define ATS 32
#define KVP 136
#define PSP 36
__global__ __launch_bounds__(128, 2)
void attn_tc(const float* __restrict__ Q, const float* __restrict__ Kb,
             const float* __restrict__ Vb, float* __restrict__ enc)
{
    __shared__ unsigned Ks[ATS * KVP];
    __shared__ unsigned Vs[ATS * KVP];
    __shared__ unsigned Ps[4][16 * PSP];

    const int b = blockIdx.z, n = blockIdx.y;
    const int tq0 = blockIdx.x * ATQ;
    const int kh = n >> 1;   // G = 2
    const int tid = threadIdx.x, warp = tid >> 5, lane = tid & 31;
    const int r0 = lane >> 2, c0 = lane & 3;
    const int trowA = tq0 + warp * 16 + r0;   // this thread's first q row
    // (second q row = trowA + 8)

    // Q fragments: 16 h-chunks of k8, 4 regs each
    unsigned qf[16][4];
    {
        const float* qbase = Q + ((size_t)(b * TOTc + tq0 + warp * 16)) * (Nh * Hd)
                               + (size_t)n * Hd;
        const size_t rs = (size_t)Nh * Hd;
#pragma unroll
        for (int hc = 0; hc < 16; hc++) {
            int col = hc * 8 + c0;
            const float* p0 = qbase + (size_t)r0 * rs + col;
            const float* p1 = qbase + (size_t)(r0 + 8) * rs + col;
            qf[hc][0] = f2tf32(p0[0]);
            qf[hc][1] = f2tf32(p1[0]);
            qf[hc][2] = f2tf32(p0[4]);
            qf[hc][3] = f2tf32(p1[4]);
        }
    }

    float oacc[16][4];
#pragma unroll
    for (int ht = 0; ht < 16; ht++)
#pragma unroll
        for (int i = 0; i < 4; i++) oacc[ht][i] = 0.f;
    float mA = -3.0e38f, mB = -3.0e38f, lA = 0.f, lB = 0.f;

    const int tmax = tq0 + ATQ - 1;

    for (int s0 = 0; s0 <= tmax; s0 += ATS) {
        // load K/V tile (32 x 128 each) as tf32 bits
        for (int i = tid; i < ATS * Hd / 4; i += 128) {
            int sr = (i * 4) >> 7;
            int cl = (i * 4) & 127;
            size_t g = ((size_t)(b * TOTc + s0 + sr)) * (Kh * Hd) + (size_t)kh * Hd + cl;
            float4 kv = *(const float4*)&Kb[g];
            float4 vv = *(const float4*)&Vb[g];
            unsigned* kd = &Ks[sr * KVP + cl];
            unsigned* vd = &Vs[sr * KVP + cl];
            kd[0]=f2tf32(kv.x); kd[1]=f2tf32(kv.y); kd[2]=f2tf32(kv.z); kd[3]=f2tf32(kv.w);
            vd[0]=f2tf32(vv.x); vd[1]=f2tf32(vv.y); vd[2]=f2tf32(vv.z); vd[3]=f2tf32(vv.w);
        }
        __syncthreads();

        // scores S[16 x 32] per warp
        float sacc[4][4];
#pragma unroll
        for (int nt = 0; nt < 4; nt++)
#pragma unroll
            for (int i = 0; i < 4; i++) sacc[nt][i] = 0.f;
#pragma unroll
        for (int hc = 0; hc < 16; hc++) {
#pragma unroll
            for (int nt = 0; nt < 4; nt++) {
                unsigned b0 = Ks[(nt * 8 + r0) * KVP + hc * 8 + c0];
                unsigned b1 = Ks[(nt * 8 + r0) * KVP + hc * 8 + c0 + 4];
                mma8(sacc[nt], qf[hc], b0, b1);
            }
        }

        // causal mask (only diagonal-adjacent tiles need it)
        if (s0 + ATS - 1 > tq0 + warp * 16) {
#pragma unroll
            for (int nt = 0; nt < 4; nt++) {
                int sA = s0 + nt * 8 + 2 * c0;
                if (sA     > trowA)     sacc[nt][0] = -3.0e38f;
                if (sA + 1 > trowA)     sacc[nt][1] = -3.0e38f;
                if (sA     > trowA + 8) sacc[nt][2] = -3.0e38f;
                if (sA + 1 > trowA + 8) sacc[nt][3] = -3.0e38f;
            }
        }

        // row maxima (4 lanes per row: xor 1, 2)
        float mx0 = fmaxf(fmaxf(sacc[0][0], sacc[0][1]), fmaxf(sacc[1][0], sacc[1][1]));
        mx0 = fmaxf(mx0, fmaxf(fmaxf(sacc[2][0], sacc[2][1]), fmaxf(sacc[3][0], sacc[3][1])));
        float mx1 = fmaxf(fmaxf(sacc[0][2], sacc[0][3]), fmaxf(sacc[1][2], sacc[1][3]));
        mx1 = fmaxf(mx1, fmaxf(fmaxf(sacc[2][2], sacc[2][3]), fmaxf(sacc[3][2], sacc[3][3])));
#pragma unroll
        for (int o = 1; o <= 2; o <<= 1) {
            mx0 = fmaxf(mx0, __shfl_xor_sync(0xffffffffu, mx0, o));
            mx1 = fmaxf(mx1, __shfl_xor_sync(0xffffffffu, mx1, o));
        }
        float nmA = fmaxf(mA, mx0), nmB = fmaxf(mB, mx1);
        float scA = __expf(mA - nmA), scB = __expf(mB - nmB);
        mA = nmA; mB = nmB;

        // probabilities + row sums; store P (tf32 bits) to per-warp smem
        float s0A = 0.f, s0B = 0.f;
        unsigned* pw = Ps[warp];
#pragma unroll
        for (int nt = 0; nt < 4; nt++) {
            float p0 = __expf(sacc[nt][0] - nmA);
            float p1 = __expf(sacc[nt][1] - nmA);
            float p2 = __expf(sacc[nt][2] - nmB);
            float p3 = __expf(sacc[nt][3] - nmB);
            s0A += p0 + p1; s0B += p2 + p3;
            int col = nt * 8 + 2 * c0;
            pw[r0 * PSP + col]           = f2tf32(p0);
            pw[r0 * PSP + col + 1]       = f2tf32(p1);
            pw[(r0 + 8) * PSP + col]     = f2tf32(p2);
            pw[(r0 + 8) * PSP + col + 1] = f2tf32(p3);
        }
#pragma unroll
        for (int o = 1; o <= 2; o <<= 1) {
            s0A += __shfl_xor_sync(0xffffffffu, s0A, o);
            s0B += __shfl_xor_sync(0xffffffffu, s0B, o);
        }
        lA = lA * scA + s0A;
        lB = lB * scB + s0B;

        // rescale O accumulators
#pragma unroll
        for (int ht = 0; ht < 16; ht++) {
            oacc[ht][0] *= scA; oacc[ht][1] *= scA;
            oacc[ht][2] *= scB; oacc[ht][3] *= scB;
        }
        __syncwarp();

        // O += P @ V   (k = 32 keys in 4 chunks, n = 128 head dims in 16 tiles)
#pragma unroll
        for (int kc = 0; kc < 4; kc++) {
            unsigned af[4];
            af[0] = pw[r0 * PSP + kc * 8 + c0];
            af[1] = pw[(r0 + 8) * PSP + kc * 8 + c0];
            af[2] = pw[r0 * PSP + kc * 8 + c0 + 4];
            af[3] = pw[(r0 + 8) * PSP + kc * 8 + c0 + 4];
#pragma unroll
            for (int ht = 0; ht < 16; ht++) {
                unsigned b0 = Vs[(kc * 8 + c0) * KVP + ht * 8 + r0];
                unsigned b1 = Vs[(kc * 8 + c0 + 4) * KVP + ht * 8 + r0];
                mma8(oacc[ht], af, b0, b1);
            }
        }
        __syncthreads();
    }

    // write output
    float invA = 1.f / lA, invB = 1.f / lB;
    const size_t baseA = ((size_t)(b * TOTc + trowA)) * (Nh * Hd) + (size_t)n * Hd;
    const size_t baseB = ((size_t)(b * TOTc + trowA + 8)) * (Nh * Hd) + (size_t)n * Hd;
#pragma unroll
    for (int ht = 0; ht < 16; ht++) {
        int cc = ht * 8 + 2 * c0;
        *(float2*)&enc[baseA + cc] = make_float2(oacc[ht][0] * invA, oacc[ht][1] * invA);
        *(float2*)&enc[baseB + cc] = make_float2(oacc[ht][2] * invB, oacc[ht][3] * invB);
    }
}

// ---------------- host orchestration ----------------
extern "C" void kernel_launch(void* const* d_in, const int* in_sizes, int n_in,
                              void* d_out, int out_size)
{
    (void)in_sizes; (void)n_in; (void)out_size;
    const float* xs[2] = {(const float*)d_in[0], (const float*)d_in[1]};
    const int*   pos   = (const int*)d_in[2];
    // d_in[3] = mask: causal lower-triangular, computed in-kernel
    const float* qw[2] = {(const float*)d_in[4],  (const float*)d_in[5]};
    const float* kw[2] = {(const float*)d_in[6],  (const float*)d_in[7]};
    const float* vw[2] = {(const float*)d_in[8],  (const float*)d_in[9]};
    const float* ow[2] = {(const float*)d_in[10], (const float*)d_in[11]};
    const float* gw[2] = {(const float*)d_in[12], (const float*)d_in[13]};
    const float* uw[2] = {(const float*)d_in[14], (const float*)d_in[15]};
    const float* dwn[2]= {(const float*)d_in[16], (const float*)d_in[17]};
    const float* pa[2] = {(const float*)d_in[18], (const float*)d_in[19]};
    const float* pf[2] = {(const float*)d_in[20], (const float*)d_in[21]};
    float* out = (float*)d_out;

    float *pre, *qb, *kb, *vb, *enc, *res, *hid, *gate, *up;
    cudaGetSymbolAddress((void**)&pre,  g_pre);
    cudaGetSymbolAddress((void**)&qb,   g_q);
    cudaGetSymbolAddress((void**)&kb,   g_k);
    cudaGetSymbolAddress((void**)&vb,   g_v);
    cudaGetSymbolAddress((void**)&enc,  g_enc);
    cudaGetSymbolAddress((void**)&res,  g_res);
    cudaGetSymbolAddress((void**)&hid,  g_hid);
    cudaGetSymbolAddress((void**)&gate, g_gate);
    cudaGetSymbolAddress((void**)&up,   g_up);

    const int Ts[2]   = {T0c, T1c};
    const int offs[2] = {0, T0c};
    const int M = Bb * T0c;   // 2048 rows per segment

    // 1) pre-attention RMSNorm
    for (int s = 0; s < 2; s++)
        rmsnorm_k<<<Bb * Ts[s], 256>>>(xs[s], pa[s], pre,
                                       Ts[s], Ts[s], 0, Ts[s], TOTc, offs[s]);

    // 2) QKV projections per segment
    for (int s = 0; s < 2; s++) {
        int off = offs[s];
        gemm_tc<<<dim3((Nh * Hd) / 128, M / 128), 256>>>(
            pre, qw[s], qb, nullptr, Nh * Hd, Dm,
            Ts[s], TOTc, off, Ts[s], TOTc, off, 1, 1, 0, 0);
        gemm_tc<<<dim3((Kh * Hd) / 128, M / 128), 256>>>(
            pre, kw[s], kb, nullptr, Kh * Hd, Dm,
            Ts[s], TOTc, off, Ts[s], TOTc, off, 1, 1, 0, 0);
        gemm_tc<<<dim3((Kh * Hd) / 128, M / 128), 256>>>(
            pre, vw[s], vb, nullptr, Kh * Hd, Dm,
            Ts[s], TOTc, off, Ts[s], TOTc, off, 1, 1, 0, 0);
    }

    // 3) RoPE (Q gets 1/sqrt(H) folded in)
    rope_k<<<Bb * TOTc * Nh, 64>>>(qb, pos, Nh, 0.08838834764831845f);
    rope_k<<<Bb * TOTc * Kh, 64>>>(kb, pos, Kh, 1.0f);

    // 4) attention (tensor-core flash)
    attn_tc<<<dim3(TOTc / ATQ, Nh, Bb), 128>>>(qb, kb, vb, enc);

    // 5) O projection + residual add of x
    for (int s = 0; s < 2; s++) {
        int off = offs[s];
        gemm_tc<<<dim3(Dm / 128, M / 128), 256>>>(
            enc, ow[s], res, xs[s], Dm, Nh * Hd,
            Ts[s], TOTc, off, Ts[s], TOTc, off, Ts[s], Ts[s], 0, 1);
    }

    // 6) pre-FFN RMSNorm
    for (int s = 0; s < 2; s++)
        rmsnorm_k<<<Bb * Ts[s], 256>>>(res, pf[s], hid,
                                       Ts[s], TOTc, offs[s], Ts[s], TOTc, offs[s]);

    // 7) FFN: gate & up GEMMs, fused gelu*up, down GEMM (+residual) -> out
    for (int s = 0; s < 2; s++) {
        int off = offs[s];
        gemm_tc<<<dim3(Ff / 128, M / 128), 256>>>(
            hid, gw[s], gate, nullptr, Ff, Dm,
            Ts[s], TOTc, off, Ts[s], Ts[s], 0, 1, 1, 0, 0);
        gemm_tc<<<dim3(Ff / 128, M / 128), 256>>>(
            hid, uw[s], up, nullptr, Ff, Dm,
            Ts[s], TOTc, off, Ts[s], Ts[s], 0, 1, 1, 0, 0);
        int n4 = (M * Ff) / 4;
        gelumul_k<<<(n4 + 255) / 256, 256>>>(gate, up, gate, n4);
        float* outseg = out + (size_t)offs[s] * Bb * Dm;
        gemm_tc<<<dim3(Dm / 128, M / 128), 256>>>(
            gate, dwn[s], outseg, res, Dm, Ff,
            Ts[s], Ts[s], 0, Ts[s], Ts[s], 0, Ts[s], TOTc, off, 1);
    }
}

// round 3
// speedup vs baseline: 3.2029x; 1.0531x over previous
#include <cuda_runtime.h>
#include <math.h>
#include <stdint.h>

// Problem constants
#define Dm   2048
#define Nh   16
#define Kh   8
#define Hd   128
#define Ff   8192
#define Bb   2
#define T0c  1024
#define T1c  1024
#define TOTc 2048

// ---------------- scratch (static device globals; no allocation) ----------
__device__ float g_pre [(size_t)Bb*TOTc*Dm];
__device__ float g_q   [(size_t)Bb*TOTc*Nh*Hd];
__device__ float g_k   [(size_t)Bb*TOTc*Kh*Hd];
__device__ float g_v   [(size_t)Bb*TOTc*Kh*Hd];
__device__ float g_enc [(size_t)Bb*TOTc*Nh*Hd];
__device__ float g_res [(size_t)Bb*TOTc*Dm];
__device__ float g_hid [(size_t)Bb*TOTc*Dm];
__device__ float g_gu  [(size_t)2*Bb*T0c*Ff];   // gate then gelu(gate)*up, both segs

__device__ __forceinline__ unsigned f2tf32(float x) {
    unsigned r;
    asm("cvt.rna.tf32.f32 %0, %1;" : "=r"(r) : "f"(x));
    return r;
}

__device__ __forceinline__ void mma8(float* c, const unsigned* a, unsigned b0, unsigned b1) {
    asm volatile(
        "mma.sync.aligned.m16n8k8.row.col.f32.tf32.tf32.f32 "
        "{%0,%1,%2,%3},{%4,%5,%6,%7},{%8,%9},{%0,%1,%2,%3};"
        : "+f"(c[0]), "+f"(c[1]), "+f"(c[2]), "+f"(c[3])
        : "r"(a[0]), "r"(a[1]), "r"(a[2]), "r"(a[3]), "r"(b0), "r"(b1));
}

__device__ __forceinline__ float gelu_t(float x) {
    float x3 = x * x * x;
    float t = tanhf(0.7978845608028654f * (x + 0.044715f * x3));
    return 0.5f * x * (1.f + t);
}

// ---------------- RMSNorm ----------------
// row remap helper for [B,TOT,D] vs [B,T,D] layouts (runtime, cheap: 1/row)
__device__ __forceinline__ int maprow(int r, int T, int TT, int off) {
    return (r / T) * TT + (r % T) + off;
}

__global__ void rmsnorm_k(const float* __restrict__ x, const float* __restrict__ sc,
                          float* __restrict__ out,
                          int iT, int iTT, int iOff, int oT, int oTT, int oOff)
{
    int r = blockIdx.x;
    const float* xi = x + (size_t)maprow(r, iT, iTT, iOff) * Dm;
    float* o = out + (size_t)maprow(r, oT, oTT, oOff) * Dm;
    __shared__ float red[256];
    float s = 0.f;
    for (int d = threadIdx.x; d < Dm; d += 256) { float v = xi[d]; s += v * v; }
    red[threadIdx.x] = s;
    __syncthreads();
    for (int st = 128; st > 0; st >>= 1) {
        if (threadIdx.x < st) red[threadIdx.x] += red[threadIdx.x + st];
        __syncthreads();
    }
    float inv = rsqrtf(red[0] / (float)Dm + 1e-6f);
    for (int d = threadIdx.x; d < Dm; d += 256)
        o[d] = xi[d] * inv * (1.f + sc[d]);
}

// ---------------- RoPE (in-place), optional output scale ----------------
__global__ void rope_k(float* __restrict__ x, const int* __restrict__ pos,
                       int nheads, float scale)
{
    int blk  = blockIdx.x;
    int head = blk % nheads;
    int bt   = blk / nheads;
    float p  = (float)pos[bt];
    float* v = x + ((size_t)bt * nheads + head) * Hd;
    int h = threadIdx.x;               // 0..63
    float fe = (2.f / (float)Hd) * (float)h;
    float inv_ts = exp2f(-fe * 13.287712379549449f);
    float rad = p * inv_ts;
    float s, c;
    sincosf(rad, &s, &c);
    float x1 = v[h], x2 = v[h + 64];
    v[h]      = (x1 * c - x2 * s) * scale;
    v[h + 64] = (x2 * c + x1 * s) * scale;
}

// ---------------- tf32 tensor-core GEMM body -------------------------------
// CTA tile 128x128, BK=16, double-buffered smem (pad 20), 8 warps = 2m x 4n,
// warp tile 64x32. All row offsets pre-resolved to per-CTA additive bases.
// mode: 0 = C=acc ; 1 = C=acc+R ; 2 = C=gelu(R)*acc
#define GPAD 20
__device__ __forceinline__ void gemm_body(
    const float* __restrict__ A, const float* __restrict__ Wt,
    float* __restrict__ C, const float* __restrict__ R,
    int Kin, int NoutC,
    int aRow0, int wRow0, int cRow0, int rRow0, int cCol0, int mode,
    unsigned* __restrict__ As, unsigned* __restrict__ Bs)
{
    const int tid  = threadIdx.x;
    const int warp = tid >> 5, lane = tid & 31;
    const int wm   = (warp & 1) * 64;
    const int wn   = (warp >> 1) * 32;
    const int r0   = lane >> 2, c0 = lane & 3;

    const int grow = tid >> 1;          // 0..127
    const int gcol = (tid & 1) * 8;     // 0 or 8
    const float* aP = A  + (size_t)(aRow0 + grow) * Kin + gcol;
    const float* wP = Wt + (size_t)(wRow0 + grow) * Kin + gcol;
    const int sW = grow * GPAD + gcol;

    float acc[4][4][4];
#pragma unroll
    for (int mt = 0; mt < 4; mt++)
#pragma unroll
        for (int nt = 0; nt < 4; nt++)
#pragma unroll
            for (int i = 0; i < 4; i++) acc[mt][nt][i] = 0.f;

    const int nk = Kin / 16;

    // prologue: tile 0 -> buffer 0
    {
        float4 a0 = *(const float4*)(aP);
        float4 a1 = *(const float4*)(aP + 4);
        float4 b0 = *(const float4*)(wP);
        float4 b1 = *(const float4*)(wP + 4);
        *(uint4*)&As[sW]     = make_uint4(f2tf32(a0.x), f2tf32(a0.y), f2tf32(a0.z), f2tf32(a0.w));
        *(uint4*)&As[sW + 4] = make_uint4(f2tf32(a1.x), f2tf32(a1.y), f2tf32(a1.z), f2tf32(a1.w));
        *(uint4*)&Bs[sW]     = make_uint4(f2tf32(b0.x), f2tf32(b0.y), f2tf32(b0.z), f2tf32(b0.w));
        *(uint4*)&Bs[sW + 4] = make_uint4(f2tf32(b1.x), f2tf32(b1.y), f2tf32(b1.z), f2tf32(b1.w));
    }
    __syncthreads();

    for (int kt = 0; kt < nk; kt++) {
        const unsigned* as = As + (kt & 1) * (128 * GPAD);
        const unsigned* bs = Bs + (kt & 1) * (128 * GPAD);
        float4 na0, na1, nb0, nb1;
        const bool more = (kt + 1 < nk);
        if (more) {
            const float* ap = aP + (size_t)(kt + 1) * 16;
            const float* bp = wP + (size_t)(kt + 1) * 16;
            na0 = *(const float4*)(ap);
            na1 = *(const float4*)(ap + 4);
            nb0 = *(const float4*)(bp);
            nb1 = *(const float4*)(bp + 4);
        }
#pragma unroll
        for (int ks = 0; ks < 2; ks++) {
            unsigned af[4][4], bf[4][2];
#pragma unroll
            for (int mt = 0; mt < 4; mt++) {
                int base = (wm + mt * 16 + r0) * GPAD + ks * 8 + c0;
                af[mt][0] = as[base];
                af[mt][1] = as[base + 8 * GPAD];
                af[mt][2] = as[base + 4];
                af[mt][3] = as[base + 8 * GPAD + 4];
            }
#pragma unroll
            for (int nt = 0; nt < 4; nt++) {
                int base = (wn + nt * 8 + r0) * GPAD + ks * 8 + c0;
                bf[nt][0] = bs[base];
                bf[nt][1] = bs[base + 4];
            }
#pragma unroll
            for (int mt = 0; mt < 4; mt++)
#pragma unroll
                for (int nt = 0; nt < 4; nt++)
                    mma8(acc[mt][nt], af[mt], bf[nt][0], bf[nt][1]);
        }
        if (more) {
            unsigned* aw = As + ((kt + 1) & 1) * (128 * GPAD) + sW;
            unsigned* bw = Bs + ((kt + 1) & 1) * (128 * GPAD) + sW;
            *(uint4*)(aw)     = make_uint4(f2tf32(na0.x), f2tf32(na0.y), f2tf32(na0.z), f2tf32(na0.w));
            *(uint4*)(aw + 4) = make_uint4(f2tf32(na1.x), f2tf32(na1.y), f2tf32(na1.z), f2tf32(na1.w));
            *(uint4*)(bw)     = make_uint4(f2tf32(nb0.x), f2tf32(nb0.y), f2tf32(nb0.z), f2tf32(nb0.w));
            *(uint4*)(bw + 4) = make_uint4(f2tf32(nb1.x), f2tf32(nb1.y), f2tf32(nb1.z), f2tf32(nb1.w));
        }
        __syncthreads();
    }

    // epilogue
#pragma unroll
    for (int mt = 0; mt < 4; mt++) {
        int rl = wm + mt * 16 + r0;
#pragma unroll
        for (int nt = 0; nt < 4; nt++) {
            int cc = cCol0 + wn + nt * 8 + 2 * c0;
            float2 v0 = make_float2(acc[mt][nt][0], acc[mt][nt][1]);
            float2 v1 = make_float2(acc[mt][nt][2], acc[mt][nt][3]);
            if (mode == 1) {
                float2 u0 = *(const float2*)&R[(size_t)(rRow0 + rl) * NoutC + cc];
                float2 u1 = *(const float2*)&R[(size_t)(rRow0 + rl + 8) * NoutC + cc];
                v0.x += u0.x; v0.y += u0.y;
                v1.x += u1.x; v1.y += u1.y;
            } else if (mode == 2) {
                float2 u0 = *(const float2*)&R[(size_t)(rRow0 + rl) * NoutC + cc];
                float2 u1 = *(const float2*)&R[(size_t)(rRow0 + rl + 8) * NoutC + cc];
                v0.x *= gelu_t(u0.x); v0.y *= gelu_t(u0.y);
                v1.x *= gelu_t(u1.x); v1.y *= gelu_t(u1.y);
            }
            *(float2*)&C[(size_t)(cRow0 + rl) * NoutC + cc]     = v0;
            *(float2*)&C[(size_t)(cRow0 + rl + 8) * NoutC + cc] = v1;
        }
    }
}

// -------- fused QKV: grid (32 n-tiles, 16 m-tiles, 2 segments) ------------
__global__ __launch_bounds__(256, 2)
void qkv_tc(const float* __restrict__ qw0, const float* __restrict__ qw1,
            const float* __restrict__ kw0, const float* __restrict__ kw1,
            const float* __restrict__ vw0, const float* __restrict__ vw1)
{
    __shared__ unsigned As[2 * 128 * GPAD];
    __shared__ unsigned Bs[2 * 128 * GPAD];
    int bn = blockIdx.x, bm = blockIdx.y * 128, z = blockIdx.z;
    const float* Wt;
    float* C;
    int NoutC, wRow0;
    if (bn < 16) {
        Wt = z ? qw1 : qw0; C = g_q; NoutC = Nh * Hd; wRow0 = bn * 128;
    } else if (bn < 24) {
        Wt = z ? kw1 : kw0; C = g_k; NoutC = Kh * Hd; wRow0 = (bn - 16) * 128;
    } else {
        Wt = z ? vw1 : vw0; C = g_v; NoutC = Kh * Hd; wRow0 = (bn - 24) * 128;
    }
    int rowTOT = bm + (bm >> 10) * 1024 + z * 1024;   // [B,TOT] layout base
    gemm_body(g_pre, Wt, C, nullptr, Dm, NoutC,
              rowTOT, wRow0, rowTOT, 0, wRow0, 0, As, Bs);
}

// -------- generic fused-2-segment GEMM ------------------------------------
// layout codes for rows: 0 = [B,TOT] interleaved (base = bm + (bm>>10)*1024 + z*1024)
//                        1 = contiguous per-seg   (base = z*2048 + bm)
//                        2 = per-seg [B,T] local  (base = bm)   (for x residual)
__global__ __launch_bounds__(256, 2)
void gemm_z(const float* __restrict__ A,
            const float* __restrict__ W0, const float* __restrict__ W1,
            float* __restrict__ C,
            const float* __restrict__ R0, const float* __restrict__ R1,
            int Kin, int NoutC, int mode, int aLay, int cLay, int rLay)
{
    __shared__ unsigned As[2 * 128 * GPAD];
    __shared__ unsigned Bs[2 * 128 * GPAD];
    int bn = blockIdx.x, bm = blockIdx.y * 128, z = blockIdx.z;
    const float* Wt = z ? W1 : W0;
    const float* R  = z ? R1 : R0;
    int rowTOT = bm + (bm >> 10) * 1024 + z * 1024;
    int rowSEG = z * 2048 + bm;
    int aRow0 = (aLay == 0) ? rowTOT : (aLay == 1 ? rowSEG : bm);
    int cRow0 = (cLay == 0) ? rowTOT : (cLay == 1 ? rowSEG : bm);
    int rRow0 = (rLay == 0) ? rowTOT : (rLay == 1 ? rowSEG : bm);
    gemm_body(A, Wt, C, R, Kin, NoutC,
              aRow0, bn * 128, cRow0, rRow0, bn * 128, mode, As, Bs);
}

// ---------------- attention: flash-style, tf32 mma ----------------
#define ATQ 64
#define ATS 32
#define KVP 136
#define PSP 36
__global__ __launch_bounds__(128, 2)
void attn_tc(const float* __restrict__ Q, const float* __restrict__ Kb,
             const float* __restrict__ Vb, float* __restrict__ enc)
{
    __shared__ unsigned Ks[ATS * KVP];
    __shared__ unsigned Vs[ATS * KVP];
    __shared__ unsigned Ps[4][16 * PSP];

    const int b = blockIdx.z, n = blockIdx.y;
    const int tq0 = blockIdx.x * ATQ;
    const int kh = n >> 1;   // G = 2
    const int tid = threadIdx.x, warp = tid >> 5, lane = tid & 31;
    const int r0 = lane >> 2, c0 = lane & 3;
    const int trowA = tq0 + warp * 16 + r0;

    unsigned qf[16][4];
    {
        const float* qbase = Q + ((size_t)(b * TOTc + tq0 + warp * 16)) * (Nh * Hd)
                               + (size_t)n * Hd;
        const size_t rs = (size_t)Nh * Hd;
#pragma unroll
        for (int hc = 0; hc < 16; hc++) {
            int col = hc * 8 + c0;
            const float* p0 = qbase + (size_t)r0 * rs + col;
            const float* p1 = qbase + (size_t)(r0 + 8) * rs + col;
            qf[hc][0] = f2tf32(p0[0]);
            qf[hc][1] = f2tf32(p1[0]);
            qf[hc][2] = f2tf32(p0[4]);
            qf[hc][3] = f2tf32(p1[4]);
        }
    }

    float oacc[16][4];
#pragma unroll
    for (int ht = 0; ht < 16; ht++)
#pragma unroll
        for (int i = 0; i < 4; i++) oacc[ht][i] = 0.f;
    float mA = -3.0e38f, mB = -3.0e38f, lA = 0.f, lB = 0.f;

    const int tmax = tq0 + ATQ - 1;

    for (int s0 = 0; s0 <= tmax; s0 += ATS) {
        for (int i = tid; i < ATS * Hd / 4; i += 128) {
            int sr = (i * 4) >> 7;
            int cl = (i * 4) & 127;
            size_t g = ((size_t)(b * TOTc + s0 + sr)) * (Kh * Hd) + (size_t)kh * Hd + cl;
            float4 kv = *(const float4*)&Kb[g];
            float4 vv = *(const float4*)&Vb[g];
            *(uint4*)&Ks[sr * KVP + cl] =
                make_uint4(f2tf32(kv.x), f2tf32(kv.y), f2tf32(kv.z), f2tf32(kv.w));
            *(uint4*)&Vs[sr * KVP + cl] =
                make_uint4(f2tf32(vv.x), f2tf32(vv.y), f2tf32(vv.z), f2tf32(vv.w));
        }
        __syncthreads();

        float sacc[4][4];
#pragma unroll
        for (int nt = 0; nt < 4; nt++)
#pragma unroll
            for (int i = 0; i < 4; i++) sacc[nt][i] = 0.f;
#pragma unroll
        for (int hc = 0; hc < 16; hc++) {
#pragma unroll
            for (int nt = 0; nt < 4; nt++) {
                unsigned b0 = Ks[(nt * 8 + r0) * KVP + hc * 8 + c0];
                unsigned b1 = Ks[(nt * 8 + r0) * KVP + hc * 8 + c0 + 4];
                mma8(sacc[nt], qf[hc], b0, b1);
            }
        }

        if (s0 + ATS - 1 > tq0 + warp * 16) {
#pragma unroll
            for (int nt = 0; nt < 4; nt++) {
                int sA = s0 + nt * 8 + 2 * c0;
                if (sA     > trowA)     sacc[nt][0] = -3.0e38f;
                if (sA + 1 > trowA)     sacc[nt][1] = -3.0e38f;
                if (sA     > trowA + 8) sacc[nt][2] = -3.0e38f;
                if (sA + 1 > trowA + 8) sacc[nt][3] = -3.0e38f;
            }
        }

        float mx0 = fmaxf(fmaxf(sacc[0][0], sacc[0][1]), fmaxf(sacc[1][0], sacc[1][1]));
        mx0 = fmaxf(mx0, fmaxf(fmaxf(sacc[2][0], sacc[2][1]), fmaxf(sacc[3][0], sacc[3][1])));
        float mx1 = fmaxf(fmaxf(sacc[0][2], sacc[0][3]), fmaxf(sacc[1][2], sacc[1][3]));
        mx1 = fmaxf(mx1, fmaxf(fmaxf(sacc[2][2], sacc[2][3]), fmaxf(sacc[3][2], sacc[3][3])));
#pragma unroll
        for (int o = 1; o <= 2; o <<= 1) {
            mx0 = fmaxf(mx0, __shfl_xor_sync(0xffffffffu, mx0, o));
            mx1 = fmaxf(mx1, __shfl_xor_sync(0xffffffffu, mx1, o));
        }
        float nmA = fmaxf(mA, mx0), nmB = fmaxf(mB, mx1);
        float scA = __expf(mA - nmA), scB = __expf(mB - nmB);
        mA = nmA; mB = nmB;

        float s0A = 0.f, s0B = 0.f;
        unsigned* pw = Ps[warp];
#pragma unroll
        for (int nt = 0; nt < 4; nt++) {
            float p0 = __expf(sacc[nt][0] - nmA);
            float p1 = __expf(sacc[nt][1] - nmA);
            float p2 = __expf(sacc[nt][2] - nmB);
            float p3 = __expf(sacc[nt][3] - nmB);
            s0A += p0 + p1; s0B += p2 + p3;
            int col = nt * 8 + 2 * c0;
            pw[r0 * PSP + col]           = f2tf32(p0);
            pw[r0 * PSP + col + 1]       = f2tf32(p1);
            pw[(r0 + 8) * PSP + col]     = f2tf32(p2);
            pw[(r0 + 8) * PSP + col + 1] = f2tf32(p3);
        }
#pragma unroll
        for (int o = 1; o <= 2; o <<= 1) {
            s0A += __shfl_xor_sync(0xffffffffu, s0A, o);
            s0B += __shfl_xor_sync(0xffffffffu, s0B, o);
        }
        lA = lA * scA + s0A;
        lB = lB * scB + s0B;

#pragma unroll
        for (int ht = 0; ht < 16; ht++) {
            oacc[ht][0] *= scA; oacc[ht][1] *= scA;
            oacc[ht][2] *= scB; oacc[ht][3] *= scB;
        }
        __syncwarp();

#pragma unroll
        for (int kc = 0; kc < 4; kc++) {
            unsigned af[4];
            af[0] = pw[r0 * PSP + kc * 8 + c0];
            af[1] = pw[(r0 + 8) * PSP + kc * 8 + c0];
            af[2] = pw[r0 * PSP + kc * 8 + c0 + 4];
            af[3] = pw[(r0 + 8) * PSP + kc * 8 + c0 + 4];
#pragma unroll
            for (int ht = 0; ht < 16; ht++) {
                unsigned b0 = Vs[(kc * 8 + c0) * KVP + ht * 8 + r0];
                unsigned b1 = Vs[(kc * 8 + c0 + 4) * KVP + ht * 8 + r0];
                mma8(oacc[ht], af, b0, b1);
            }
        }
        __syncthreads();
    }

    float invA = 1.f / lA, invB = 1.f / lB;
    const size_t baseA = ((size_t)(b * TOTc + trowA)) * (Nh * Hd) + (size_t)n * Hd;
    const size_t baseB = ((size_t)(b * TOTc + trowA + 8)) * (Nh * Hd) + (size_t)n * Hd;
#pragma unroll
    for (int ht = 0; ht < 16; ht++) {
        int cc = ht * 8 + 2 * c0;
        *(float2*)&enc[baseA + cc] = make_float2(oacc[ht][0] * invA, oacc[ht][1] * invA);
        *(float2*)&enc[baseB + cc] = make_float2(oacc[ht][2] * invB, oacc[ht][3] * invB);
    }
}

// ---------------- host orchestration ----------------
extern "C" void kernel_launch(void* const* d_in, const int* in_sizes, int n_in,
                              void* d_out, int out_size)
{
    (void)in_sizes; (void)n_in; (void)out_size;
    const float* xs[2] = {(const float*)d_in[0], (const float*)d_in[1]};
    const int*   pos   = (const int*)d_in[2];
    // d_in[3] = mask: causal lower-triangular, computed in-kernel
    const float* qw[2] = {(const float*)d_in[4],  (const float*)d_in[5]};
    const float* kw[2] = {(const float*)d_in[6],  (const float*)d_in[7]};
    const float* vw[2] = {(const float*)d_in[8],  (const float*)d_in[9]};
    const float* ow[2] = {(const float*)d_in[10], (const float*)d_in[11]};
    const float* gw[2] = {(const float*)d_in[12], (const float*)d_in[13]};
    const float* uw[2] = {(const float*)d_in[14], (const float*)d_in[15]};
    const float* dwn[2]= {(const float*)d_in[16], (const float*)d_in[17]};
    const float* pa[2] = {(const float*)d_in[18], (const float*)d_in[19]};
    const float* pf[2] = {(const float*)d_in[20], (const float*)d_in[21]};
    float* out = (float*)d_out;

    float *pre, *qb, *kb, *vb, *enc, *res, *hid, *gu;
    cudaGetSymbolAddress((void**)&pre, g_pre);
    cudaGetSymbolAddress((void**)&qb,  g_q);
    cudaGetSymbolAddress((void**)&kb,  g_k);
    cudaGetSymbolAddress((void**)&vb,  g_v);
    cudaGetSymbolAddress((void**)&enc, g_enc);
    cudaGetSymbolAddress((void**)&res, g_res);
    cudaGetSymbolAddress((void**)&hid, g_hid);
    cudaGetSymbolAddress((void**)&gu,  g_gu);

    const int Ts[2]   = {T0c, T1c};
    const int offs[2] = {0, T0c};

    // 1) pre-attention RMSNorm
    for (int s = 0; s < 2; s++)
        rmsnorm_k<<<Bb * Ts[s], 256>>>(xs[s], pa[s], pre,
                                       Ts[s], Ts[s], 0, Ts[s], TOTc, offs[s]);

    // 2) fused QKV projection, both segments
    qkv_tc<<<dim3(32, 16, 2), 256>>>(qw[0], qw[1], kw[0], kw[1], vw[0], vw[1]);

    // 3) RoPE (Q gets 1/sqrt(H) folded in)
    rope_k<<<Bb * TOTc * Nh, 64>>>(qb, pos, Nh, 0.08838834764831845f);
    rope_k<<<Bb * TOTc * Kh, 64>>>(kb, pos, Kh, 1.0f);

    // 4) attention (tensor-core flash)
    attn_tc<<<dim3(TOTc / ATQ, Nh, Bb), 128>>>(qb, kb, vb, enc);

    // 5) O projection + residual add of x  (A=enc TOT, C=res TOT, R=x per-seg)
    gemm_z<<<dim3(Dm / 128, 16, 2), 256>>>(enc, ow[0], ow[1], res, xs[0], xs[1],
                                           Nh * Hd, Dm, 1, 0, 0, 2);

    // 6) pre-FFN RMSNorm
    for (int s = 0; s < 2; s++)
        rmsnorm_k<<<Bb * Ts[s], 256>>>(res, pf[s], hid,
                                       Ts[s], TOTc, offs[s], Ts[s], TOTc, offs[s]);

    // 7) FFN: gate -> gu ; up (epilogue gelu(gate)*up) -> gu ; down + residual -> out
    gemm_z<<<dim3(Ff / 128, 16, 2), 256>>>(hid, gw[0], gw[1], gu, nullptr, nullptr,
                                           Dm, Ff, 0, 0, 1, 1);
    gemm_z<<<dim3(Ff / 128, 16, 2), 256>>>(hid, uw[0], uw[1], gu, gu, gu,
                                           Dm, Ff, 2, 0, 1, 1);
    gemm_z<<<dim3(Dm / 128, 16, 2), 256>>>(gu, dwn[0], dwn[1], out, res, res,
                                           Ff, Dm, 1, 1, 1, 0);
}